// round 17
// baseline (speedup 1.0000x reference)
#include <cuda_runtime.h>
#include <math.h>

#define NB 2
#define RR 360
#define RRH 180
#define NN 100
#define SS 200
#define KXN 101
#define NPIX (NN*NN)
#define NLIGH (NB*RRH*2)
#define NIMGH (NLIGH + NB*2)
#define GPITCH 102
#define RT2 0.70710678118654752f

__device__ float  d_h1[4][9][NPIX];
__device__ float  d_feat[4][2][NPIX];
__device__ float2 d_G[NIMGH][NN][GPITCH];
__device__ float2 d_F[NIMGH][KXN][SS];
__device__ float2 d_H[NB*RR][KXN][SS];
__device__ unsigned int d_best[NB];
__device__ float  d_pos[NB];

__device__ __forceinline__ unsigned fenc(float f) {
    unsigned u = __float_as_uint(f);
    return (u & 0x80000000u) ? ~u : (u | 0x80000000u);
}
__device__ __forceinline__ float fdec(unsigned e) {
    unsigned u = (e & 0x80000000u) ? (e & 0x7FFFFFFFu) : ~e;
    return __uint_as_float(u);
}

__global__ void k_init() {
    int t = threadIdx.x;
    if (t < NB) { d_best[t] = 0u; d_pos[t] = 0.0f; }
}

// ---------------- conv1 + norm_relu (FIELDS1) -------------------------------
__global__ void k_conv1(const float* __restrict__ rec, const float* __restrict__ lig,
                        const float* __restrict__ w1) {
    int img = blockIdx.y;
    int p = blockIdx.x * blockDim.x + threadIdx.x;
    if (p >= NPIX) return;
    int y = p / NN, x = p % NN;
    const float* src = (img < NB) ? (rec + img * NPIX) : (lig + (img - NB) * NPIX);
    float acc[9];
#pragma unroll
    for (int o = 0; o < 9; o++) acc[o] = 0.0f;
#pragma unroll
    for (int ky = 0; ky < 5; ky++) {
        int iy = y + ky - 2;
        if ((unsigned)iy >= NN) continue;
#pragma unroll
        for (int kx = 0; kx < 5; kx++) {
            int ix = x + kx - 2;
            if ((unsigned)ix >= NN) continue;
            float v = __ldg(src + iy * NN + ix);
#pragma unroll
            for (int o = 0; o < 9; o++)
                acc[o] = fmaf(v, __ldg(w1 + o * 25 + ky * 5 + kx), acc[o]);
        }
    }
    {
        float a = acc[0];
        float n = sqrtf(a * a + 1e-12f);
        d_h1[img][0][p] = a * (n / (n + 1e-12f));
    }
#pragma unroll
    for (int g = 0; g < 4; g++) {
        int s = 1 + 2 * g;
        float a = acc[s], b = acc[s + 1];
        float n = sqrtf(a * a + b * b + 1e-12f);
        float sc = n / (n + 1e-12f);
        d_h1[img][s][p] = a * sc;
        d_h1[img][s + 1][p] = b * sc;
    }
}

// ---------------- conv2 + norm_relu (FIELDS2) + features --------------------
__global__ void k_conv2(const float* __restrict__ w2) {
    int img = blockIdx.y;
    int p = blockIdx.x * blockDim.x + threadIdx.x;
    if (p >= NPIX) return;
    int y = p / NN, x = p % NN;
    float acc[3] = {0.f, 0.f, 0.f};
    for (int ci = 0; ci < 9; ci++) {
        const float* hp = d_h1[img][ci];
#pragma unroll
        for (int ky = 0; ky < 5; ky++) {
            int iy = y + ky - 2;
            if ((unsigned)iy >= NN) continue;
#pragma unroll
            for (int kx = 0; kx < 5; kx++) {
                int ix = x + kx - 2;
                if ((unsigned)ix >= NN) continue;
                float v = hp[iy * NN + ix];
#pragma unroll
                for (int o = 0; o < 3; o++)
                    acc[o] = fmaf(v, __ldg(w2 + ((o * 9 + ci) * 5 + ky) * 5 + kx), acc[o]);
            }
        }
    }
    float o0, o1, o2;
    {
        float a = acc[0];
        float n = sqrtf(a * a + 1e-12f);
        o0 = a * (n / (n + 1e-12f));
    }
    {
        float a = acc[1], b = acc[2];
        float n = sqrtf(a * a + b * b + 1e-12f);
        float sc = n / (n + 1e-12f);
        o1 = a * sc; o2 = b * sc;
    }
    d_feat[img][0][p] = fabsf(o0);
    d_feat[img][1][p] = sqrtf(o1 * o1 + o2 * o2 + 1e-12f);
}

__device__ __forceinline__ float samp(const float* __restrict__ im, float yf, float xf) {
    if (yf < 0.f || yf >= 100.f || xf < 0.f || xf >= 100.f) return 0.f;
    int yc = (int)yf, xc = (int)xf;
    return im[yc * NN + xc];
}

// Complex accumulate with explicit twiddle (2 complex vals per float4)
#define CACC4(Tr, Ti, f4, twr, twi) \
    Tr[2*q]   = fmaf((f4).x, twr, Tr[2*q]);   Tr[2*q]   = fmaf(-(f4).y, twi, Tr[2*q]); \
    Ti[2*q]   = fmaf((f4).x, twi, Ti[2*q]);   Ti[2*q]   = fmaf( (f4).y, twr, Ti[2*q]); \
    Tr[2*q+1] = fmaf((f4).z, twr, Tr[2*q+1]); Tr[2*q+1] = fmaf(-(f4).w, twi, Tr[2*q+1]); \
    Ti[2*q+1] = fmaf((f4).z, twi, Ti[2*q+1]); Ti[2*q+1] = fmaf( (f4).w, twr, Ti[2*q+1]);

// Real-input accumulate, 4 y-lanes (float4 of real values)
#define RACCF4(Ur, Ui, f4) \
    Ur[0] = fmaf((f4).x, wsr, Ur[0]); Ui[0] = fmaf((f4).x, wsi, Ui[0]); \
    Ur[1] = fmaf((f4).y, wsr, Ur[1]); Ui[1] = fmaf((f4).y, wsi, Ui[1]); \
    Ur[2] = fmaf((f4).z, wsr, Ur[2]); Ui[2] = fmaf((f4).z, wsi, Ui[2]); \
    Ur[3] = fmaf((f4).w, wsr, Ur[3]); Ui[3] = fmaf((f4).w, wsi, Ui[3]);

// ---------------- rotate (fused) + row DFT, RADIX-8 (real input) ------------
// x = 8s+c (rotT zero-padded to 104 rows). S_c = sum_s rot[8s+c] W^s (real),
// W = e^{-2pi i u/25}. T_c = w^c S_c, w = e^{-i pi u/100}.
// G[u+25j] = sum_c T_c e^{-i pi c j/4}; store j=0..3 (+ j=4 for u=0 -> kx=100).
__global__ void __launch_bounds__(256) k_rot_rowdft() {
    __shared__ __align__(16) float rotT[104 * 104];   // [x][y], pitch 104
    int bid = blockIdx.x;
    int tid = threadIdx.x;
    const float* src;
    bool ident;
    float ct = 1.f, st = 0.f;
    if (bid < NLIGH) {
        int c = bid & 1;
        int r = (bid >> 1) % RRH;
        int b = bid / (2 * RRH);
        src = d_feat[NB + b][c];
        double th = -3.14159265358979323846 + (double)r * (6.283185307179586477 / 360.0);
        ct = (float)cos(th); st = (float)sin(th);
        ident = false;
    } else {
        int i = bid - NLIGH;
        src = d_feat[i >> 1][i & 1];
        ident = true;
    }
    for (int p = tid; p < 104 * 104; p += 256) rotT[p] = 0.f;
    __syncthreads();
    for (int p = tid; p < NPIX; p += blockDim.x) {
        int i = p / NN, j = p % NN;
        float val;
        if (ident) {
            val = src[p];
        } else {
            float xs = (float)j - 49.5f, ys = (float)i - 49.5f;
            float xq = ct * xs + st * ys + 49.5f;
            float yq = -st * xs + ct * ys + 49.5f;
            float x0f = floorf(xq), y0f = floorf(yq);
            float wx = xq - x0f, wy = yq - y0f;
            val = samp(src, y0f, x0f) * (1.f - wy) * (1.f - wx)
                + samp(src, y0f, x0f + 1.f) * (1.f - wy) * wx
                + samp(src, y0f + 1.f, x0f) * wy * (1.f - wx)
                + samp(src, y0f + 1.f, x0f + 1.f) * wy * wx;
        }
        rotT[j * 104 + i] = val;   // transposed: row = x, col = y
    }
    __syncthreads();
    // 625 tasks = 25 y-groups of 4 x 25 u (u fastest)
    for (int task = tid; task < 625; task += 256) {
        int u = task % 25;
        int y0 = (task / 25) * 4;
        int uw = (u > 12) ? u - 25 : u;
        float Wi_, Wr_;
        sincosf(-6.28318530717959f * (float)uw * 0.04f, &Wi_, &Wr_);   // W = e^{-2pi i u/25}
        float wsr = 1.f, wsi = 0.f;
        float S0r[4], S0i[4], S1r[4], S1i[4], S2r[4], S2i[4], S3r[4], S3i[4];
        float S4r[4], S4i[4], S5r[4], S5i[4], S6r[4], S6i[4], S7r[4], S7i[4];
#pragma unroll
        for (int j = 0; j < 4; j++) {
            S0r[j]=S0i[j]=S1r[j]=S1i[j]=S2r[j]=S2i[j]=S3r[j]=S3i[j]=0.f;
            S4r[j]=S4i[j]=S5r[j]=S5i[j]=S6r[j]=S6i[j]=S7r[j]=S7i[j]=0.f;
        }
        for (int t = 0; t < 13; t++) {
            float4 v0 = *reinterpret_cast<const float4*>(&rotT[(8*t    ) * 104 + y0]); RACCF4(S0r, S0i, v0)
            float4 v1 = *reinterpret_cast<const float4*>(&rotT[(8*t + 1) * 104 + y0]); RACCF4(S1r, S1i, v1)
            float4 v2 = *reinterpret_cast<const float4*>(&rotT[(8*t + 2) * 104 + y0]); RACCF4(S2r, S2i, v2)
            float4 v3 = *reinterpret_cast<const float4*>(&rotT[(8*t + 3) * 104 + y0]); RACCF4(S3r, S3i, v3)
            float4 v4 = *reinterpret_cast<const float4*>(&rotT[(8*t + 4) * 104 + y0]); RACCF4(S4r, S4i, v4)
            float4 v5 = *reinterpret_cast<const float4*>(&rotT[(8*t + 5) * 104 + y0]); RACCF4(S5r, S5i, v5)
            float4 v6 = *reinterpret_cast<const float4*>(&rotT[(8*t + 6) * 104 + y0]); RACCF4(S6r, S6i, v6)
            float4 v7 = *reinterpret_cast<const float4*>(&rotT[(8*t + 7) * 104 + y0]); RACCF4(S7r, S7i, v7)
            float nsr = wsr * Wr_ - wsi * Wi_;
            float nsi = wsr * Wi_ + wsi * Wr_;
            wsr = nsr; wsi = nsi;
        }
        float w1r_, w1i_, w2r_, w2i_;
        sincosf(-3.14159265358979f * (float)u * 0.01f, &w1i_, &w1r_);  // w
        sincosf(-3.14159265358979f * (float)u * 0.02f, &w2i_, &w2r_);  // w^2
        float w3r_ = w1r_*w2r_ - w1i_*w2i_, w3i_ = w1r_*w2i_ + w1i_*w2r_;
        float w4r_ = w2r_*w2r_ - w2i_*w2i_, w4i_ = 2.f*w2r_*w2i_;
        float w5r_ = w2r_*w3r_ - w2i_*w3i_, w5i_ = w2r_*w3i_ + w2i_*w3r_;
        float w6r_ = w3r_*w3r_ - w3i_*w3i_, w6i_ = 2.f*w3r_*w3i_;
        float w7r_ = w3r_*w4r_ - w3i_*w4i_, w7i_ = w3r_*w4i_ + w3i_*w4r_;
#pragma unroll
        for (int i = 0; i < 4; i++) {
            int y = y0 + i;
            if (y >= NN) continue;
            float V1r = w1r_*S1r[i] - w1i_*S1i[i], V1i = w1r_*S1i[i] + w1i_*S1r[i];
            float V2r = w2r_*S2r[i] - w2i_*S2i[i], V2i = w2r_*S2i[i] + w2i_*S2r[i];
            float V3r = w3r_*S3r[i] - w3i_*S3i[i], V3i = w3r_*S3i[i] + w3i_*S3r[i];
            float V4r = w4r_*S4r[i] - w4i_*S4i[i], V4i = w4r_*S4i[i] + w4i_*S4r[i];
            float V5r = w5r_*S5r[i] - w5i_*S5i[i], V5i = w5r_*S5i[i] + w5i_*S5r[i];
            float V6r = w6r_*S6r[i] - w6i_*S6i[i], V6i = w6r_*S6i[i] + w6i_*S6r[i];
            float V7r = w7r_*S7r[i] - w7i_*S7i[i], V7i = w7r_*S7i[i] + w7i_*S7r[i];
            float acr = S0r[i] + V4r, aci = S0i[i] + V4i;
            float amr = S0r[i] - V4r, ami = S0i[i] - V4i;
            float bdr = V2r + V6r, bdi = V2i + V6i;
            float bmr = V2r - V6r, bmi = V2i - V6i;
            float E0r = acr + bdr, E0i = aci + bdi;
            float E1r = amr + bmi, E1i = ami - bmr;       // am - i*bm (forward)
            float E2r = acr - bdr, E2i = aci - bdi;
            float E3r = amr - bmi, E3i = ami + bmr;       // am + i*bm
            float pcr = V1r + V5r, pci = V1i + V5i;
            float pmr = V1r - V5r, pmi = V1i - V5i;
            float qdr = V3r + V7r, qdi = V3i + V7i;
            float qmr = V3r - V7r, qmi = V3i - V7i;
            float G0r = pcr + qdr, G0i = pci + qdi;
            float G1r = pmr + qmi, G1i = pmi - qmr;       // pm - i*qm
            float G2r = pcr - qdr, G2i = pci - qdi;
            float G3r = pmr - qmi, G3i = pmi + qmr;       // pm + i*qm
            float O0r = G0r,                O0i = G0i;
            float O1r = RT2 * (G1r + G1i),  O1i = RT2 * (G1i - G1r);    // e^{-i pi/4} G1
            float O2r = G2i,                O2i = -G2r;                 // -i G2
            float O3r = RT2 * (G3i - G3r),  O3i = -RT2 * (G3r + G3i);   // e^{-3i pi/4} G3
            d_G[bid][y][u]      = make_float2(E0r + O0r, E0i + O0i);
            d_G[bid][y][u + 25] = make_float2(E1r + O1r, E1i + O1i);
            d_G[bid][y][u + 50] = make_float2(E2r + O2r, E2i + O2i);
            d_G[bid][y][u + 75] = make_float2(E3r + O3r, E3i + O3i);
            if (u == 0)
                d_G[bid][y][100] = make_float2(E0r - O0r, E0i - O0i);
        }
    }
}

// ---------------- column DFT, RADIX-8 (forward) -----------------------------
__global__ void __launch_bounds__(256) k_coldft() {
    __shared__ __align__(16) float2 GT[104][56];
    int img = blockIdx.x >> 1;
    int half = blockIdx.x & 1;
    int kxg0 = half * 52;
    int width = half ? 49 : 52;
    int tid = threadIdx.x;
    for (int t = tid; t < 104 * 56; t += 256) {
        int y = t / 56, kxl = t % 56;
        float2 v = make_float2(0.f, 0.f);
        if (y < NN && kxl < width) v = d_G[img][y][kxg0 + kxl];
        GT[y][kxl] = v;
    }
    __syncthreads();
    for (int task = tid; task < 650; task += 256) {
        int u = task % 25;
        int kxl0 = (task / 25) * 2;
        int uw = (u > 12) ? u - 25 : u;
        float Wi_, Wr_;
        sincosf(-6.28318530717959f * (float)uw * 0.04f, &Wi_, &Wr_);
        float wsr = 1.f, wsi = 0.f;
        float S0r[2], S0i[2], S1r[2], S1i[2], S2r[2], S2i[2], S3r[2], S3i[2];
        float S4r[2], S4i[2], S5r[2], S5i[2], S6r[2], S6i[2], S7r[2], S7i[2];
#pragma unroll
        for (int j = 0; j < 2; j++) {
            S0r[j]=S0i[j]=S1r[j]=S1i[j]=S2r[j]=S2i[j]=S3r[j]=S3i[j]=0.f;
            S4r[j]=S4i[j]=S5r[j]=S5i[j]=S6r[j]=S6i[j]=S7r[j]=S7i[j]=0.f;
        }
        for (int t = 0; t < 13; t++) {
            const int q = 0;
            float4 e0 = *reinterpret_cast<const float4*>(&GT[8*t    ][kxl0]); CACC4(S0r, S0i, e0, wsr, wsi)
            float4 e1 = *reinterpret_cast<const float4*>(&GT[8*t + 1][kxl0]); CACC4(S1r, S1i, e1, wsr, wsi)
            float4 e2 = *reinterpret_cast<const float4*>(&GT[8*t + 2][kxl0]); CACC4(S2r, S2i, e2, wsr, wsi)
            float4 e3 = *reinterpret_cast<const float4*>(&GT[8*t + 3][kxl0]); CACC4(S3r, S3i, e3, wsr, wsi)
            float4 e4 = *reinterpret_cast<const float4*>(&GT[8*t + 4][kxl0]); CACC4(S4r, S4i, e4, wsr, wsi)
            float4 e5 = *reinterpret_cast<const float4*>(&GT[8*t + 5][kxl0]); CACC4(S5r, S5i, e5, wsr, wsi)
            float4 e6 = *reinterpret_cast<const float4*>(&GT[8*t + 6][kxl0]); CACC4(S6r, S6i, e6, wsr, wsi)
            float4 e7 = *reinterpret_cast<const float4*>(&GT[8*t + 7][kxl0]); CACC4(S7r, S7i, e7, wsr, wsi)
            float nsr = wsr * Wr_ - wsi * Wi_;
            float nsi = wsr * Wi_ + wsi * Wr_;
            wsr = nsr; wsi = nsi;
        }
        float w1r_, w1i_, w2r_, w2i_;
        sincosf(-3.14159265358979f * (float)u * 0.01f, &w1i_, &w1r_);
        sincosf(-3.14159265358979f * (float)u * 0.02f, &w2i_, &w2r_);
        float w3r_ = w1r_*w2r_ - w1i_*w2i_, w3i_ = w1r_*w2i_ + w1i_*w2r_;
        float w4r_ = w2r_*w2r_ - w2i_*w2i_, w4i_ = 2.f*w2r_*w2i_;
        float w5r_ = w2r_*w3r_ - w2i_*w3i_, w5i_ = w2r_*w3i_ + w2i_*w3r_;
        float w6r_ = w3r_*w3r_ - w3i_*w3i_, w6i_ = 2.f*w3r_*w3i_;
        float w7r_ = w3r_*w4r_ - w3i_*w4i_, w7i_ = w3r_*w4i_ + w3i_*w4r_;
#pragma unroll
        for (int jj = 0; jj < 2; jj++) {
            int kxl = kxl0 + jj;
            if (kxl >= width) continue;
            int kx = kxg0 + kxl;
            float V1r = w1r_*S1r[jj] - w1i_*S1i[jj], V1i = w1r_*S1i[jj] + w1i_*S1r[jj];
            float V2r = w2r_*S2r[jj] - w2i_*S2i[jj], V2i = w2r_*S2i[jj] + w2i_*S2r[jj];
            float V3r = w3r_*S3r[jj] - w3i_*S3i[jj], V3i = w3r_*S3i[jj] + w3i_*S3r[jj];
            float V4r = w4r_*S4r[jj] - w4i_*S4i[jj], V4i = w4r_*S4i[jj] + w4i_*S4r[jj];
            float V5r = w5r_*S5r[jj] - w5i_*S5i[jj], V5i = w5r_*S5i[jj] + w5i_*S5r[jj];
            float V6r = w6r_*S6r[jj] - w6i_*S6i[jj], V6i = w6r_*S6i[jj] + w6i_*S6r[jj];
            float V7r = w7r_*S7r[jj] - w7i_*S7i[jj], V7i = w7r_*S7i[jj] + w7i_*S7r[jj];
            float acr = S0r[jj] + V4r, aci = S0i[jj] + V4i;
            float amr = S0r[jj] - V4r, ami = S0i[jj] - V4i;
            float bdr = V2r + V6r, bdi = V2i + V6i;
            float bmr = V2r - V6r, bmi = V2i - V6i;
            float E0r = acr + bdr, E0i = aci + bdi;
            float E2r = acr - bdr, E2i = aci - bdi;
            float E1r = amr + bmi, E1i = ami - bmr;
            float E3r = amr - bmi, E3i = ami + bmr;
            float pcr = V1r + V5r, pci = V1i + V5i;
            float pmr = V1r - V5r, pmi = V1i - V5i;
            float qdr = V3r + V7r, qdi = V3i + V7i;
            float qmr = V3r - V7r, qmi = V3i - V7i;
            float G0r = pcr + qdr, G0i = pci + qdi;
            float G2r = pcr - qdr, G2i = pci - qdi;
            float G1r = pmr + qmi, G1i = pmi - qmr;
            float G3r = pmr - qmi, G3i = pmi + qmr;
            float O0r = G0r,                O0i = G0i;
            float O1r = RT2 * (G1r + G1i),  O1i = RT2 * (G1i - G1r);
            float O2r = G2i,                O2i = -G2r;
            float O3r = RT2 * (G3i - G3r),  O3i = -RT2 * (G3r + G3i);
            d_F[img][kx][u]       = make_float2(E0r + O0r, E0i + O0i);
            d_F[img][kx][u + 100] = make_float2(E0r - O0r, E0i - O0i);
            d_F[img][kx][u + 25]  = make_float2(E1r + O1r, E1i + O1i);
            d_F[img][kx][u + 125] = make_float2(E1r - O1r, E1i - O1i);
            d_F[img][kx][u + 50]  = make_float2(E2r + O2r, E2i + O2i);
            d_F[img][kx][u + 150] = make_float2(E2r - O2r, E2i - O2i);
            d_F[img][kx][u + 75]  = make_float2(E3r + O3r, E3i + O3i);
            d_F[img][kx][u + 175] = make_float2(E3r - O3r, E3i - O3i);
        }
    }
}

// ---------------- combine spectra + inverse ky (RADIX-8) --------------------
__global__ void __launch_bounds__(320) k_combine_invy(const float* __restrict__ wb,
        const float* __restrict__ wc1, const float* __restrict__ wc2,
        const float* __restrict__ wk) {
    __shared__ __align__(16) float2 sfs[SS][24];
    __shared__ float2 ph[304];
    int chunk = blockIdx.x % 5;
    int imgH = blockIdx.x / 5;
    int b = imgH / RR;
    int r = imgH % RR;
    bool flip = (r >= RRH);
    int rb180 = flip ? r - RRH : r;
    int kxg0 = chunk * 24;
    int width = (KXN - kxg0 < 24) ? (KXN - kxg0) : 24;
    int tid = threadIdx.x;
    float w0 = *wb, w1v = *wc1, w2v = *wc2, w3v = *wk;
    int imgL0 = (b * RRH + rb180) * 2, imgL1 = imgL0 + 1;
    int imgR0 = NLIGH + b * 2, imgR1 = imgR0 + 1;
    if (flip) {
        for (int s = tid; s < 301; s += 320) {
            float pr, pi_;
            sincosf(3.14159265358979f * 0.01f * (float)s, &pi_, &pr);
            if (s & 1) { pr = -pr; pi_ = -pi_; }
            ph[s] = make_float2(pr, pi_);
        }
        __syncthreads();
    }
    for (int e = tid; e < SS * 24; e += 320) {
        int ky = e % SS, kxl = e / SS;
        float2 v = make_float2(0.f, 0.f);
        if (kxl < width) {
            int kx = kxg0 + kxl;
            float2 lb = d_F[imgL0][kx][ky];
            float2 lB = d_F[imgL1][kx][ky];
            if (flip) {
                float2 p = ph[kx + ky];
                float t;
                t    = p.x * lb.x + p.y * lb.y;
                lb.y = p.y * lb.x - p.x * lb.y;
                lb.x = t;
                t    = p.x * lB.x + p.y * lB.y;
                lB.y = p.y * lB.x - p.x * lB.y;
                lB.x = t;
            }
            float2 rb = d_F[imgR0][kx][ky];
            float2 rB = d_F[imgR1][kx][ky];
            float ur = w0 * lb.x + w1v * lB.x, ui = w0 * lb.y + w1v * lB.y;
            float vr = w2v * lb.x - w3v * lB.x, vi = w2v * lb.y - w3v * lB.y;
            v.x = rb.x * ur + rb.y * ui + rB.x * vr + rB.y * vi;
            v.y = rb.x * ui - rb.y * ur + rB.x * vi - rB.y * vr;
        }
        sfs[ky][kxl] = v;
    }
    __syncthreads();
    for (int task = tid; task < 300; task += 320) {
        int v = task % 25;
        int kxl0 = (task / 25) * 2;
        int vw = (v > 12) ? v - 25 : v;
        float Wi_, Wr_;
        sincosf(6.28318530717959f * (float)vw * 0.04f, &Wi_, &Wr_);
        float wsr = 1.f, wsi = 0.f;
        float S0r[2], S0i[2], S1r[2], S1i[2], S2r[2], S2i[2], S3r[2], S3i[2];
        float S4r[2], S4i[2], S5r[2], S5i[2], S6r[2], S6i[2], S7r[2], S7i[2];
#pragma unroll
        for (int j = 0; j < 2; j++) {
            S0r[j]=S0i[j]=S1r[j]=S1i[j]=S2r[j]=S2i[j]=S3r[j]=S3i[j]=0.f;
            S4r[j]=S4i[j]=S5r[j]=S5i[j]=S6r[j]=S6i[j]=S7r[j]=S7i[j]=0.f;
        }
        for (int t = 0; t < 25; t++) {
            const int q = 0;
            float4 e0 = *reinterpret_cast<const float4*>(&sfs[8*t    ][kxl0]); CACC4(S0r, S0i, e0, wsr, wsi)
            float4 e1 = *reinterpret_cast<const float4*>(&sfs[8*t + 1][kxl0]); CACC4(S1r, S1i, e1, wsr, wsi)
            float4 e2 = *reinterpret_cast<const float4*>(&sfs[8*t + 2][kxl0]); CACC4(S2r, S2i, e2, wsr, wsi)
            float4 e3 = *reinterpret_cast<const float4*>(&sfs[8*t + 3][kxl0]); CACC4(S3r, S3i, e3, wsr, wsi)
            float4 e4 = *reinterpret_cast<const float4*>(&sfs[8*t + 4][kxl0]); CACC4(S4r, S4i, e4, wsr, wsi)
            float4 e5 = *reinterpret_cast<const float4*>(&sfs[8*t + 5][kxl0]); CACC4(S5r, S5i, e5, wsr, wsi)
            float4 e6 = *reinterpret_cast<const float4*>(&sfs[8*t + 6][kxl0]); CACC4(S6r, S6i, e6, wsr, wsi)
            float4 e7 = *reinterpret_cast<const float4*>(&sfs[8*t + 7][kxl0]); CACC4(S7r, S7i, e7, wsr, wsi)
            float nsr = wsr * Wr_ - wsi * Wi_;
            float nsi = wsr * Wi_ + wsi * Wr_;
            wsr = nsr; wsi = nsi;
        }
        float w1r_, w1i_, w2r_, w2i_;
        sincosf(3.14159265358979f * (float)v * 0.01f, &w1i_, &w1r_);
        sincosf(3.14159265358979f * (float)v * 0.02f, &w2i_, &w2r_);
        float w3r_ = w1r_*w2r_ - w1i_*w2i_, w3i_ = w1r_*w2i_ + w1i_*w2r_;
        float w4r_ = w2r_*w2r_ - w2i_*w2i_, w4i_ = 2.f*w2r_*w2i_;
        float w5r_ = w2r_*w3r_ - w2i_*w3i_, w5i_ = w2r_*w3i_ + w2i_*w3r_;
        float w6r_ = w3r_*w3r_ - w3i_*w3i_, w6i_ = 2.f*w3r_*w3i_;
        float w7r_ = w3r_*w4r_ - w3i_*w4i_, w7i_ = w3r_*w4i_ + w3i_*w4r_;
#pragma unroll
        for (int jj = 0; jj < 2; jj++) {
            int kxl = kxl0 + jj;
            if (kxl >= width) continue;
            int kx = kxg0 + kxl;
            float V1r = w1r_*S1r[jj] - w1i_*S1i[jj], V1i = w1r_*S1i[jj] + w1i_*S1r[jj];
            float V2r = w2r_*S2r[jj] - w2i_*S2i[jj], V2i = w2r_*S2i[jj] + w2i_*S2r[jj];
            float V3r = w3r_*S3r[jj] - w3i_*S3i[jj], V3i = w3r_*S3i[jj] + w3i_*S3r[jj];
            float V4r = w4r_*S4r[jj] - w4i_*S4i[jj], V4i = w4r_*S4i[jj] + w4i_*S4r[jj];
            float V5r = w5r_*S5r[jj] - w5i_*S5i[jj], V5i = w5r_*S5i[jj] + w5i_*S5r[jj];
            float V6r = w6r_*S6r[jj] - w6i_*S6i[jj], V6i = w6r_*S6i[jj] + w6i_*S6r[jj];
            float V7r = w7r_*S7r[jj] - w7i_*S7i[jj], V7i = w7r_*S7i[jj] + w7i_*S7r[jj];
            float acr = S0r[jj] + V4r, aci = S0i[jj] + V4i;
            float amr = S0r[jj] - V4r, ami = S0i[jj] - V4i;
            float bdr = V2r + V6r, bdi = V2i + V6i;
            float bmr = V2r - V6r, bmi = V2i - V6i;
            float E0r = acr + bdr, E0i = aci + bdi;
            float E2r = acr - bdr, E2i = aci - bdi;
            float E1r = amr - bmi, E1i = ami + bmr;
            float E3r = amr + bmi, E3i = ami - bmr;
            float pcr = V1r + V5r, pci = V1i + V5i;
            float pmr = V1r - V5r, pmi = V1i - V5i;
            float qdr = V3r + V7r, qdi = V3i + V7i;
            float qmr = V3r - V7r, qmi = V3i - V7i;
            float G0r = pcr + qdr, G0i = pci + qdi;
            float G2r = pcr - qdr, G2i = pci - qdi;
            float G1r = pmr - qmi, G1i = pmi + qmr;
            float G3r = pmr + qmi, G3i = pmi - qmr;
            float O0r = G0r,               O0i = G0i;
            float O1r = RT2 * (G1r - G1i), O1i = RT2 * (G1r + G1i);
            float O2r = -G2i,              O2i = G2r;
            float O3r = -RT2 * (G3r + G3i), O3i = RT2 * (G3r - G3i);
            d_H[imgH][kx][v]       = make_float2(E0r + O0r, E0i + O0i);
            d_H[imgH][kx][v + 100] = make_float2(E0r - O0r, E0i - O0i);
            d_H[imgH][kx][v + 25]  = make_float2(E1r + O1r, E1i + O1i);
            d_H[imgH][kx][v + 125] = make_float2(E1r - O1r, E1i - O1i);
            d_H[imgH][kx][v + 50]  = make_float2(E2r + O2r, E2i + O2i);
            d_H[imgH][kx][v + 150] = make_float2(E2r - O2r, E2i - O2i);
            d_H[imgH][kx][v + 75]  = make_float2(E3r + O3r, E3i + O3i);
            d_H[imgH][kx][v + 175] = make_float2(E3r - O3r, E3i - O3i);
        }
    }
}

// ---------------- inverse kx (real, RADIX-8) + reduce -----------------------
__global__ void __launch_bounds__(256) k_invx_reduce(const int* __restrict__ gtr,
                                                     const int* __restrict__ gtt) {
    __shared__ __align__(16) float2 HT[104][20];
    __shared__ float red[256];
    int yc = blockIdx.x % 10;
    int imgH = blockIdx.x / 10;
    int b = imgH / RR, r = imgH % RR;
    int ybase = yc * 20;
    int tid = threadIdx.x;
    for (int e = tid; e < 104 * 20; e += 256) {
        int kx = e / 20, yl = e % 20;
        float2 val = make_float2(0.f, 0.f);
        if (kx < KXN) {
            val = d_H[imgH][kx][ybase + yl];
            if (kx == 0 || kx == 100) { val.x *= 0.5f; val.y *= 0.5f; }
        }
        HT[kx][yl] = val;
    }
    __syncthreads();
    int gr = gtr[b], t0 = gtt[2 * b], t1 = gtt[2 * b + 1];
    const float inv = 1.0f / 40000.0f;
    float lmax = -3.4e38f;
    for (int task = tid; task < 250; task += 256) {
        int v = task % 25;
        int y0 = (task / 25) * 2;
        int vw = (v > 12) ? v - 25 : v;
        float Wi_, Wr_;
        sincosf(6.28318530717959f * (float)vw * 0.04f, &Wi_, &Wr_);
        float wsr = 1.f, wsi = 0.f;
        float Z0r[2], Z0i[2], Z1r[2], Z1i[2], Z2r[2], Z2i[2], Z3r[2], Z3i[2];
        float Z4r[2], Z4i[2], Z5r[2], Z5i[2], Z6r[2], Z6i[2], Z7r[2], Z7i[2];
#pragma unroll
        for (int j = 0; j < 2; j++) {
            Z0r[j]=Z0i[j]=Z1r[j]=Z1i[j]=Z2r[j]=Z2i[j]=Z3r[j]=Z3i[j]=0.f;
            Z4r[j]=Z4i[j]=Z5r[j]=Z5i[j]=Z6r[j]=Z6i[j]=Z7r[j]=Z7i[j]=0.f;
        }
        for (int t = 0; t < 13; t++) {
            const int q = 0;
            float4 h0 = *reinterpret_cast<const float4*>(&HT[8*t    ][y0]); CACC4(Z0r, Z0i, h0, wsr, wsi)
            float4 h1 = *reinterpret_cast<const float4*>(&HT[8*t + 1][y0]); CACC4(Z1r, Z1i, h1, wsr, wsi)
            float4 h2 = *reinterpret_cast<const float4*>(&HT[8*t + 2][y0]); CACC4(Z2r, Z2i, h2, wsr, wsi)
            float4 h3 = *reinterpret_cast<const float4*>(&HT[8*t + 3][y0]); CACC4(Z3r, Z3i, h3, wsr, wsi)
            float4 h4 = *reinterpret_cast<const float4*>(&HT[8*t + 4][y0]); CACC4(Z4r, Z4i, h4, wsr, wsi)
            float4 h5 = *reinterpret_cast<const float4*>(&HT[8*t + 5][y0]); CACC4(Z5r, Z5i, h5, wsr, wsi)
            float4 h6 = *reinterpret_cast<const float4*>(&HT[8*t + 6][y0]); CACC4(Z6r, Z6i, h6, wsr, wsi)
            float4 h7 = *reinterpret_cast<const float4*>(&HT[8*t + 7][y0]); CACC4(Z7r, Z7i, h7, wsr, wsi)
            float nsr = wsr * Wr_ - wsi * Wi_;
            float nsi = wsr * Wi_ + wsi * Wr_;
            wsr = nsr; wsi = nsi;
        }
        float w1r_, w1i_, w2r_, w2i_;
        sincosf(3.14159265358979f * (float)v * 0.01f, &w1i_, &w1r_);
        sincosf(3.14159265358979f * (float)v * 0.02f, &w2i_, &w2r_);
        float w3r_ = w1r_*w2r_ - w1i_*w2i_, w3i_ = w1r_*w2i_ + w1i_*w2r_;
        float w4r_ = w2r_*w2r_ - w2i_*w2i_, w4i_ = 2.f*w2r_*w2i_;
        float w5r_ = w2r_*w3r_ - w2i_*w3i_, w5i_ = w2r_*w3i_ + w2i_*w3r_;
        float w6r_ = w3r_*w3r_ - w3i_*w3i_, w6i_ = 2.f*w3r_*w3i_;
        float w7r_ = w3r_*w4r_ - w3i_*w4i_, w7i_ = w3r_*w4i_ + w3i_*w4r_;
#pragma unroll
        for (int i = 0; i < 2; i++) {
            float V1r = w1r_*Z1r[i] - w1i_*Z1i[i], V1i = w1r_*Z1i[i] + w1i_*Z1r[i];
            float V2r = w2r_*Z2r[i] - w2i_*Z2i[i], V2i = w2r_*Z2i[i] + w2i_*Z2r[i];
            float V3r = w3r_*Z3r[i] - w3i_*Z3i[i], V3i = w3r_*Z3i[i] + w3i_*Z3r[i];
            float V4r = w4r_*Z4r[i] - w4i_*Z4i[i], V4i = w4r_*Z4i[i] + w4i_*Z4r[i];
            float V5r = w5r_*Z5r[i] - w5i_*Z5i[i], V5i = w5r_*Z5i[i] + w5i_*Z5r[i];
            float V6r = w6r_*Z6r[i] - w6i_*Z6i[i], V6i = w6r_*Z6i[i] + w6i_*Z6r[i];
            float V7r = w7r_*Z7r[i] - w7i_*Z7i[i], V7i = w7r_*Z7i[i] + w7i_*Z7r[i];
            float acr = Z0r[i] + V4r, aci = Z0i[i] + V4i;
            float amr = Z0r[i] - V4r, ami = Z0i[i] - V4i;
            float bdr = V2r + V6r, bdi = V2i + V6i;
            float bmr = V2r - V6r, bmi = V2i - V6i;
            float E0r = acr + bdr;
            float E2r = acr - bdr;
            float E1r = amr - bmi;
            float E3r = amr + bmi;
            float pcr = V1r + V5r, pci = V1i + V5i;
            float pmr = V1r - V5r, pmi = V1i - V5i;
            float qdr = V3r + V7r, qdi = V3i + V7i;
            float qmr = V3r - V7r, qmi = V3i - V7i;
            float G0r = pcr + qdr;
            float G2i = pci - qdi;
            float G1r = pmr - qmi, G1i = pmi + qmr;
            float G3r = pmr + qmi, G3i = pmi - qmr;
            float O0r = G0r;
            float O1r = RT2 * (G1r - G1i);
            float O2r = -G2i;
            float O3r = -RT2 * (G3r + G3i);
            float sc = 2.f * inv;
            float s[8];
            s[0] = (E0r + O0r) * sc;  s[4] = (E0r - O0r) * sc;
            s[1] = (E1r + O1r) * sc;  s[5] = (E1r - O1r) * sc;
            s[2] = (E2r + O2r) * sc;  s[6] = (E2r - O2r) * sc;
            s[3] = (E3r + O3r) * sc;  s[7] = (E3r - O3r) * sc;
#pragma unroll
            for (int j = 0; j < 8; j++) lmax = fmaxf(lmax, s[j]);
            int y = ybase + y0 + i;
            if (r == gr && y == t0) {
#pragma unroll
                for (int j = 0; j < 8; j++)
                    if (v + 25 * j == t1) d_pos[b] = s[j];
            }
        }
    }
    red[tid] = lmax;
    __syncthreads();
    for (int s2 = 128; s2 > 0; s2 >>= 1) {
        if (tid < s2) red[tid] = fmaxf(red[tid], red[tid + s2]);
        __syncthreads();
    }
    if (tid == 0) atomicMax(&d_best[b], fenc(red[0]));
}

__global__ void k_final(float* __restrict__ out) {
    if (threadIdx.x == 0) {
        float lp = 0.f, ln = 0.f;
        for (int b = 0; b < NB; b++) {
            float p = d_pos[b];
            lp += p + p * p;
            float m = fdec(d_best[b]);
            ln += -m + m * m;
        }
        out[0] = lp / (float)NB;
        out[1] = ln / (float)NB;
    }
}

extern "C" void kernel_launch(void* const* d_in, const int* in_sizes, int n_in,
                              void* d_out, int out_size) {
    const float* rec = (const float*)d_in[0];
    const float* lig = (const float*)d_in[1];
    const float* w1 = (const float*)d_in[2];
    const float* w2 = (const float*)d_in[3];
    const float* wb = (const float*)d_in[4];
    const float* wc1 = (const float*)d_in[5];
    const float* wc2 = (const float*)d_in[6];
    const float* wk = (const float*)d_in[7];
    const int* gtr = (const int*)d_in[8];
    const int* gtt = (const int*)d_in[9];
    float* out = (float*)d_out;

    k_init<<<1, 32>>>();
    dim3 gconv((NPIX + 255) / 256, 4);
    k_conv1<<<gconv, 256>>>(rec, lig, w1);
    k_conv2<<<gconv, 256>>>(w2);
    k_rot_rowdft<<<NIMGH, 256>>>();
    k_coldft<<<NIMGH * 2, 256>>>();
    k_combine_invy<<<NB * RR * 5, 320>>>(wb, wc1, wc2, wk);
    k_invx_reduce<<<NB * RR * 10, 256>>>(gtr, gtt);
    k_final<<<1, 32>>>(out);
}